// round 15
// baseline (speedup 1.0000x reference)
#include <cuda_runtime.h>
#include <cuda_bf16.h>
#include <math.h>
#include <stdint.h>

// Shapes (fixed by the benchmark)
#define BB 2
#define SS 8192
#define DD 64
#define D2 128           // 2*D

// Smem layout: 4 bf16 tiles, 256B rows, XOR-swizzled in 16B units
#define OFF_QH 0          // 128 x 128 bf16 = 32KB
#define OFF_QL 32768
#define OFF_KH 65536      // 64 x 128 bf16 = 16KB
#define OFF_KL 81920
#define SM_BYTES 98304

// Work chunking: q-tile m (0..63) has NJ=2(m+1) kv-steps, split into cn=m/8+1 chunks
// (each chunk <= 16 steps). NWORK = sum_m (m/8+1) = 8*(1+..+8) = 288.
#define NWORK 288
#define NSLICE 8

// EMA chunking
#define EMA_CHUNK 128
#define EMA_NCHUNK (SS / EMA_CHUNK)   // 64

// Scratch (static device globals -- no allocation allowed)
__device__ __nv_bfloat16 g_Qh[BB * SS * D2];
__device__ __nv_bfloat16 g_Ql[BB * SS * D2];
__device__ __nv_bfloat16 g_Kh[BB * SS * D2];
__device__ __nv_bfloat16 g_Kl[BB * SS * D2];
__device__ float g_O4[NSLICE][BB * SS * DD];  // unnormalized folded O per chunk slice
__device__ float g_Ls4[NSLICE][BB * SS];      // row exp-sums per chunk slice

// ---------------- helpers ----------------
__device__ __forceinline__ uint32_t smem_u32(const void* p) {
    uint32_t a;
    asm("{ .reg .u64 t; cvta.to.shared.u64 t, %1; cvt.u32.u64 %0, t; }"
        : "=r"(a) : "l"(p));
    return a;
}
__device__ __forceinline__ void ldsm4(uint32_t* r, uint32_t addr) {
    asm volatile("ldmatrix.sync.aligned.m8n8.x4.shared.b16 {%0,%1,%2,%3}, [%4];"
        : "=r"(r[0]), "=r"(r[1]), "=r"(r[2]), "=r"(r[3]) : "r"(addr));
}
__device__ __forceinline__ void ldsm4t(uint32_t* r, uint32_t addr) {
    asm volatile("ldmatrix.sync.aligned.m8n8.x4.trans.shared.b16 {%0,%1,%2,%3}, [%4];"
        : "=r"(r[0]), "=r"(r[1]), "=r"(r[2]), "=r"(r[3]) : "r"(addr));
}
__device__ __forceinline__ void mma16816(float* c, const uint32_t* a, const uint32_t* b) {
    asm volatile(
        "mma.sync.aligned.m16n8k16.row.col.f32.bf16.bf16.f32 "
        "{%0,%1,%2,%3}, {%4,%5,%6,%7}, {%8,%9}, {%0,%1,%2,%3};"
        : "+f"(c[0]), "+f"(c[1]), "+f"(c[2]), "+f"(c[3])
        : "r"(a[0]), "r"(a[1]), "r"(a[2]), "r"(a[3]), "r"(b[0]), "r"(b[1]));
}
// pack (x -> lo, y -> hi) as bf16x2, plus residual pack
__device__ __forceinline__ void split2(float x, float y, uint32_t& h, uint32_t& l) {
    asm("cvt.rn.bf16x2.f32 %0, %1, %2;" : "=r"(h) : "f"(y), "f"(x));
    float hx = __uint_as_float(h << 16);
    float hy = __uint_as_float(h & 0xffff0000u);
    asm("cvt.rn.bf16x2.f32 %0, %1, %2;" : "=r"(l) : "f"(y - hy), "f"(x - hx));
}

// -------------------- Kernel 1: prep Q (LUT cos) and K, bf16 hi/lo --------------------
__global__ void prep_kernel(const float* __restrict__ sr,
                            const float* __restrict__ si,
                            const float* __restrict__ pos,
                            const float* __restrict__ w_q,
                            const float* __restrict__ b_q) {
    const float PHI_F     = (float)1.6180339887498948482;
    const float INV2PI    = (float)(1.0 / 6.283185307179586476925286766559);
    const float LUTN_F    = 4096.0f;
    const float ANG_STEP  = (float)(6.283185307179586476925286766559 / 4096.0);

    int idx = blockIdx.x * blockDim.x + threadIdx.x;   // over B*S*D
    if (idx >= BB * SS * DD) return;
    int d = idx & (DD - 1);
    int s = (idx >> 6) & (SS - 1);
    int b = idx >> 19;

    float wl   = 1.0f + fabsf(w_q[d]);
    float bq   = b_q[d];
    float tphi = __fmul_rn(pos[s], PHI_F);

    float xr = sr[idx];
    float xi = si[idx];

    float thr = __fadd_rn(__fadd_rn(__fdiv_rn(xr, wl), bq), tphi);
    float thi = __fadd_rn(__fadd_rn(__fdiv_rn(xi, wl), bq), tphi);

    float fr = __fmul_rn(thr, INV2PI);
    fr = __fsub_rn(fr, floorf(fr));
    int ir = (int)floorf(__fmul_rn(fr, LUTN_F));
    ir = ir < 0 ? 0 : (ir > 4095 ? 4095 : ir);
    float cr = cosf(__fmul_rn((float)ir, ANG_STEP));

    float fi = __fmul_rn(thi, INV2PI);
    fi = __fsub_rn(fi, floorf(fi));
    int ii = (int)floorf(__fmul_rn(fi, LUTN_F));
    ii = ii < 0 ? 0 : (ii > 4095 ? 4095 : ii);
    float ci = cosf(__fmul_rn((float)ii, ANG_STEP));

    int base = (b * SS + s) * D2;

    __nv_bfloat16 h, l;
    h = __float2bfloat16_rn(cr); l = __float2bfloat16_rn(cr - __bfloat162float(h));
    g_Qh[base + d] = h; g_Ql[base + d] = l;
    h = __float2bfloat16_rn(ci); l = __float2bfloat16_rn(ci - __bfloat162float(h));
    g_Qh[base + d + DD] = h; g_Ql[base + d + DD] = l;
    h = __float2bfloat16_rn(xr); l = __float2bfloat16_rn(xr - __bfloat162float(h));
    g_Kh[base + d] = h; g_Kl[base + d] = l;
    h = __float2bfloat16_rn(xi); l = __float2bfloat16_rn(xi - __bfloat162float(h));
    g_Kh[base + d + DD] = h; g_Kl[base + d + DD] = l;
}

// ============ Kernel 2: causal flash attention (mma.sync bf16 split, chunked KV) ============
__global__ __launch_bounds__(256, 1) void attn_mma() {
    extern __shared__ char sm[];
    const uint32_t su = smem_u32(sm);
    const uint32_t sQh_u = su + OFF_QH, sQl_u = su + OFF_QL;
    const uint32_t sKh_u = su + OFF_KH, sKl_u = su + OFF_KL;

    const int tid  = threadIdx.x;
    const int wid  = tid >> 5;
    const int lane = tid & 31;
    const int lr = lane & 7, q4 = lane >> 3;
    const int g  = lane >> 2, t = lane & 3;

    // ---- work item decode: largest-m chunks first ----
    // bucket p = m/8 (0..7): 8 m-values x (p+1) chunks; item count before
    // bucket p is off(p) = 8*(1+..+p) = 4p(p+1).
    const int bid = blockIdx.x;
    const int b   = bid & 1;
    const int w   = (NWORK - 1) - (bid >> 1);   // 0..287
    int p = 0;
    while (4 * (p + 1) * (p + 2) <= w) p++;     // bucket index 0..7
    const int q  = w - 4 * p * (p + 1);
    const int cn = p + 1;
    const int m  = 8 * p + q / cn;
    const int ci = q % cn;
    const int NJ = 2 * (m + 1);                 // kv-steps for this tile
    const int q0 = m << 7;
    const int j0 = (ci * NJ) / cn;
    const int j1 = ((ci + 1) * NJ) / cn;

    const char* Qhg = (const char*)(g_Qh + b * (SS * D2) + q0 * D2);
    const char* Qlg = (const char*)(g_Ql + b * (SS * D2) + q0 * D2);
    const char* Khg = (const char*)(g_Kh + b * (SS * D2));
    const char* Klg = (const char*)(g_Kl + b * (SS * D2));

    // ---- load Q tiles (128 rows x 256B), swizzled ----
    for (int e = tid; e < 2048; e += 256) {
        int r = e >> 4, u = e & 15;
        int so = r * 256 + ((u ^ (r & 7)) << 4);
        int go = r * 256 + u * 16;
        *(uint4*)(sm + OFF_QH + so) = *(const uint4*)(Qhg + go);
        *(uint4*)(sm + OFF_QL + so) = *(const uint4*)(Qlg + go);
    }

    // A-frag (Q) lane addressing
    const int rowA = wid * 16 + lr + 8 * (q4 & 1);
    const int swA = rowA & 7;
    const int unitAx = q4 >> 1;
    const uint32_t aRow = (uint32_t)rowA * 256u;
    // B-frag (K rows as n) lane addressing
    const int rowBo = lr + 8 * (q4 >> 1);
    const int unitBx = q4 & 1;
    // V-frag (trans) lane addressing
    const int rowVo = lr + 8 * (q4 & 1);
    const int unitVx = q4 >> 1;

    float o[16][4];
    #pragma unroll
    for (int i = 0; i < 16; i++)
        #pragma unroll
        for (int c = 0; c < 4; c++) o[i][c] = 0.f;
    float l0 = 0.f, l1 = 0.f;

    const float SC = 0.0883883476483184405501f;  // 1/sqrt(128)
    const int row0 = q0 + wid * 16 + g;

    for (int j = j0; j < j1; ++j) {
        const int k0 = j << 6;
        if (j > j0) __syncthreads();
        // ---- load K tiles (64 rows x 256B), hi+lo ----
        for (int e = tid; e < 1024; e += 256) {
            int r = e >> 4, u = e & 15;
            int so = r * 256 + ((u ^ (r & 7)) << 4);
            int go = (k0 + r) * 256 + u * 16;
            *(uint4*)(sm + OFF_KH + so) = *(const uint4*)(Khg + go);
            *(uint4*)(sm + OFF_KL + so) = *(const uint4*)(Klg + go);
        }
        __syncthreads();

        // ---- QK: S[16x64] = Qh.Kh + Qh.Kl + Ql.Kh ----
        float s[8][4];
        #pragma unroll
        for (int i = 0; i < 8; i++)
            #pragma unroll
            for (int c = 0; c < 4; c++) s[i][c] = 0.f;

        #pragma unroll
        for (int kb = 0; kb < 8; kb++) {
            uint32_t aH[4], aL[4];
            uint32_t ao = aRow + (uint32_t)(((2 * kb + unitAx) ^ swA) << 4);
            ldsm4(aH, sQh_u + ao);
            ldsm4(aL, sQl_u + ao);
            #pragma unroll
            for (int nb2 = 0; nb2 < 4; nb2++) {
                int rB = nb2 * 16 + rowBo;
                uint32_t bo = (uint32_t)(rB * 256 + (((2 * kb + unitBx) ^ (rB & 7)) << 4));
                uint32_t bH[4], bL[4];
                ldsm4(bH, sKh_u + bo);
                ldsm4(bL, sKl_u + bo);
                mma16816(s[2 * nb2],     aH, &bH[0]);
                mma16816(s[2 * nb2],     aH, &bL[0]);
                mma16816(s[2 * nb2],     aL, &bH[0]);
                mma16816(s[2 * nb2 + 1], aH, &bH[2]);
                mma16816(s[2 * nb2 + 1], aH, &bL[2]);
                mma16816(s[2 * nb2 + 1], aL, &bH[2]);
            }
        }

        // ---- epilogue: mask + exp + build P frags in registers ----
        uint32_t ph0[8], ph1[8], pl0[8], pl1[8];
        const bool full = (k0 + 63 <= q0 + wid * 16);
        #pragma unroll
        for (int nb = 0; nb < 8; nb++) {
            float e0, e1, e2, e3;
            if (full) {
                e0 = __expf(s[nb][0] * SC);
                e1 = __expf(s[nb][1] * SC);
                e2 = __expf(s[nb][2] * SC);
                e3 = __expf(s[nb][3] * SC);
            } else {
                int col = k0 + nb * 8 + 2 * t;
                e0 = (col     <= row0    ) ? __expf(s[nb][0] * SC) : 0.f;
                e1 = (col + 1 <= row0    ) ? __expf(s[nb][1] * SC) : 0.f;
                e2 = (col     <= row0 + 8) ? __expf(s[nb][2] * SC) : 0.f;
                e3 = (col + 1 <= row0 + 8) ? __expf(s[nb][3] * SC) : 0.f;
            }
            l0 += e0 + e1;
            l1 += e2 + e3;
            split2(e0, e1, ph0[nb], pl0[nb]);
            split2(e2, e3, ph1[nb], pl1[nb]);
        }

        // ---- PV: O[16x128] += Ph.Vh + Ph.Vl + Pl.Vh  (V = K tile, trans frags) ----
        #pragma unroll
        for (int kb = 0; kb < 4; kb++) {
            uint32_t aPh[4] = { ph0[2 * kb], ph1[2 * kb], ph0[2 * kb + 1], ph1[2 * kb + 1] };
            uint32_t aPl[4] = { pl0[2 * kb], pl1[2 * kb], pl0[2 * kb + 1], pl1[2 * kb + 1] };
            #pragma unroll
            for (int db2 = 0; db2 < 8; db2++) {
                int rV = kb * 16 + rowVo;
                uint32_t vo = (uint32_t)(rV * 256 + (((2 * db2 + unitVx) ^ (rV & 7)) << 4));
                uint32_t bH[4], bL[4];
                ldsm4t(bH, sKh_u + vo);
                ldsm4t(bL, sKl_u + vo);
                mma16816(o[2 * db2],     aPh, &bH[0]);
                mma16816(o[2 * db2],     aPh, &bL[0]);
                mma16816(o[2 * db2],     aPl, &bH[0]);
                mma16816(o[2 * db2 + 1], aPh, &bH[2]);
                mma16816(o[2 * db2 + 1], aPh, &bL[2]);
                mma16816(o[2 * db2 + 1], aPl, &bH[2]);
            }
        }
    }

    // ---- row-sum reduce (across the 4 lanes sharing a row) ----
    l0 += __shfl_xor_sync(0xffffffffu, l0, 1);
    l0 += __shfl_xor_sync(0xffffffffu, l0, 2);
    l1 += __shfl_xor_sync(0xffffffffu, l1, 1);
    l1 += __shfl_xor_sync(0xffffffffu, l1, 2);

    // ---- fold (c and c+64) in registers, write slice ci ----
    float* Og = &g_O4[ci][b * (SS * DD)];
    #pragma unroll
    for (int dt = 0; dt < 8; dt++) {
        int c = dt * 8 + 2 * t;   // 0..63
        float f0 = o[dt][0] + o[dt + 8][0];
        float f1 = o[dt][1] + o[dt + 8][1];
        float f2 = o[dt][2] + o[dt + 8][2];
        float f3 = o[dt][3] + o[dt + 8][3];
        *(float2*)(Og + row0 * DD + c)       = make_float2(f0, f1);
        *(float2*)(Og + (row0 + 8) * DD + c) = make_float2(f2, f3);
    }
    if (t == 0) {
        g_Ls4[ci][b * SS + row0]     = l0;
        g_Ls4[ci][b * SS + row0 + 8] = l1;
    }
}

// ------ Kernel 3: combine slices + chunked EMA (windowed, batch-prefetched) ------
__global__ __launch_bounds__(64, 1) void ema_chunk_kernel(
        const float* __restrict__ alpha_p, float* __restrict__ out) {
    const int d     = threadIdx.x;              // 0..63
    const int b     = blockIdx.x >> 6;
    const int chunk = blockIdx.x & 63;

    const float alpha = alpha_p[0];
    const float a  = 1.0f / (1.0f + expf(-alpha));
    const float na = 1.0f - a;

    // adaptive lookback: (1-a)^lb <= 2^-40, rounded to 8, clamped
    float dl = -log2f(na);
    int lb = (int)ceilf(40.0f / fmaxf(dl, 1e-6f));
    lb = (lb + 7) & ~7;
    lb = lb < 8 ? 8 : (lb > 2048 ? 2048 : lb);

    const int t0     = chunk * EMA_CHUNK;
    int tstart       = t0 - lb;
    if (tstart < 0) tstart = 0;
    const int tend   = t0 + EMA_CHUNK;

    const int bO = b * (SS * DD);
    const int bL = b * SS;
    float* __restrict__ Ob = out + b * (SS * DD);

    float e = 0.f;
    for (int t = tstart; t < tend; t += 8) {
        float z[8];
        #pragma unroll
        for (int i = 0; i < 8; i++) {
            const int tt = t + i;
            const int cn = ((tt >> 7) >> 3) + 1;   // m/8 + 1 slices for this q-tile
            float num = g_O4[0][bO + tt * DD + d];
            float L   = g_Ls4[0][bL + tt];
            for (int s2 = 1; s2 < cn; s2++) {
                num += g_O4[s2][bO + tt * DD + d];
                L   += g_Ls4[s2][bL + tt];
            }
            z[i] = num / L;
        }
        #pragma unroll
        for (int i = 0; i < 8; i++) {
            e = a * z[i] + na * e;
            if (t + i >= t0) Ob[(t + i) * DD + d] = e;
        }
    }
}

// -------------------- launch --------------------
extern "C" void kernel_launch(void* const* d_in, const int* in_sizes, int n_in,
                              void* d_out, int out_size) {
    const float* sr    = (const float*)d_in[0];
    const float* si    = (const float*)d_in[1];
    const float* pos   = (const float*)d_in[2];
    const float* w_q   = (const float*)d_in[3];
    const float* b_q   = (const float*)d_in[4];
    const float* alpha = (const float*)d_in[5];
    float* out = (float*)d_out;

    (void)in_sizes; (void)n_in; (void)out_size;

    cudaFuncSetAttribute(attn_mma,
                         cudaFuncAttributeMaxDynamicSharedMemorySize, SM_BYTES);

    const int nprep = BB * SS * DD;
    prep_kernel<<<(nprep + 255) / 256, 256>>>(sr, si, pos, w_q, b_q);
    attn_mma<<<2 * NWORK, 256, SM_BYTES>>>();
    ema_chunk_kernel<<<BB * EMA_NCHUNK, 64>>>(alpha, out);
}

// round 16
// speedup vs baseline: 2.0238x; 2.0238x over previous
#include <cuda_runtime.h>
#include <cuda_bf16.h>
#include <math.h>
#include <stdint.h>

// Shapes (fixed by the benchmark)
#define BB 2
#define SS 8192
#define DD 64
#define D2 128           // 2*D

// Smem: Q tiles (64KB) + 3-slot K ring (3 x 32KB)
#define OFF_QH 0          // 128 x 128 bf16 = 32KB
#define OFF_QL 32768
#define OFFK(s) (65536 + (s) * 32768)   // per slot: KH at +0, KL at +16384
#define SM_BYTES 163840

// EMA chunking
#define EMA_CHUNK 128
#define EMA_NCHUNK (SS / EMA_CHUNK)   // 64

// Scratch (static device globals -- no allocation allowed)
__device__ __nv_bfloat16 g_Qh[BB * SS * D2];
__device__ __nv_bfloat16 g_Ql[BB * SS * D2];
__device__ __nv_bfloat16 g_Kh[BB * SS * D2];
__device__ __nv_bfloat16 g_Kl[BB * SS * D2];
__device__ float g_O[2][BB * SS * DD];   // unnormalized folded O per kv-split
__device__ float g_Ls[2][BB * SS];       // row exp-sums per split

// ---------------- helpers ----------------
__device__ __forceinline__ uint32_t smem_u32(const void* p) {
    uint32_t a;
    asm("{ .reg .u64 t; cvta.to.shared.u64 t, %1; cvt.u32.u64 %0, t; }"
        : "=r"(a) : "l"(p));
    return a;
}
__device__ __forceinline__ void ldsm4(uint32_t* r, uint32_t addr) {
    asm volatile("ldmatrix.sync.aligned.m8n8.x4.shared.b16 {%0,%1,%2,%3}, [%4];"
        : "=r"(r[0]), "=r"(r[1]), "=r"(r[2]), "=r"(r[3]) : "r"(addr));
}
__device__ __forceinline__ void ldsm4t(uint32_t* r, uint32_t addr) {
    asm volatile("ldmatrix.sync.aligned.m8n8.x4.trans.shared.b16 {%0,%1,%2,%3}, [%4];"
        : "=r"(r[0]), "=r"(r[1]), "=r"(r[2]), "=r"(r[3]) : "r"(addr));
}
__device__ __forceinline__ void mma16816(float* c, const uint32_t* a, const uint32_t* b) {
    asm volatile(
        "mma.sync.aligned.m16n8k16.row.col.f32.bf16.bf16.f32 "
        "{%0,%1,%2,%3}, {%4,%5,%6,%7}, {%8,%9}, {%0,%1,%2,%3};"
        : "+f"(c[0]), "+f"(c[1]), "+f"(c[2]), "+f"(c[3])
        : "r"(a[0]), "r"(a[1]), "r"(a[2]), "r"(a[3]), "r"(b[0]), "r"(b[1]));
}
// pack (x -> lo, y -> hi) as bf16x2, plus residual pack
__device__ __forceinline__ void split2(float x, float y, uint32_t& h, uint32_t& l) {
    asm("cvt.rn.bf16x2.f32 %0, %1, %2;" : "=r"(h) : "f"(y), "f"(x));
    float hx = __uint_as_float(h << 16);
    float hy = __uint_as_float(h & 0xffff0000u);
    asm("cvt.rn.bf16x2.f32 %0, %1, %2;" : "=r"(l) : "f"(y - hy), "f"(x - hx));
}
// async copy of one K tile (hi+lo, 32KB) into ring slot base kbase_u
__device__ __forceinline__ void issue_ktile(const char* Khg, const char* Klg,
                                            uint32_t kbase_u, int k0, int tid) {
    #pragma unroll
    for (int e0 = 0; e0 < 1024; e0 += 256) {
        int e = e0 + tid;
        int r = e >> 4, u = e & 15;
        uint32_t so = (uint32_t)(r * 256 + ((u ^ (r & 7)) << 4));
        const char* gh = Khg + (size_t)(k0 + r) * 256 + (size_t)u * 16;
        const char* gl = Klg + (size_t)(k0 + r) * 256 + (size_t)u * 16;
        asm volatile("cp.async.cg.shared.global [%0], [%1], 16;"
                     :: "r"(kbase_u + so), "l"(gh));
        asm volatile("cp.async.cg.shared.global [%0], [%1], 16;"
                     :: "r"(kbase_u + 16384 + so), "l"(gl));
    }
}

// -------------------- Kernel 1: prep Q (LUT cos) and K, bf16 hi/lo --------------------
__global__ void prep_kernel(const float* __restrict__ sr,
                            const float* __restrict__ si,
                            const float* __restrict__ pos,
                            const float* __restrict__ w_q,
                            const float* __restrict__ b_q) {
    const float PHI_F     = (float)1.6180339887498948482;
    const float INV2PI    = (float)(1.0 / 6.283185307179586476925286766559);
    const float LUTN_F    = 4096.0f;
    const float ANG_STEP  = (float)(6.283185307179586476925286766559 / 4096.0);

    int idx = blockIdx.x * blockDim.x + threadIdx.x;   // over B*S*D
    if (idx >= BB * SS * DD) return;
    int d = idx & (DD - 1);
    int s = (idx >> 6) & (SS - 1);
    int b = idx >> 19;

    float wl   = 1.0f + fabsf(w_q[d]);
    float bq   = b_q[d];
    float tphi = __fmul_rn(pos[s], PHI_F);

    float xr = sr[idx];
    float xi = si[idx];

    float thr = __fadd_rn(__fadd_rn(__fdiv_rn(xr, wl), bq), tphi);
    float thi = __fadd_rn(__fadd_rn(__fdiv_rn(xi, wl), bq), tphi);

    float fr = __fmul_rn(thr, INV2PI);
    fr = __fsub_rn(fr, floorf(fr));
    int ir = (int)floorf(__fmul_rn(fr, LUTN_F));
    ir = ir < 0 ? 0 : (ir > 4095 ? 4095 : ir);
    float cr = cosf(__fmul_rn((float)ir, ANG_STEP));

    float fi = __fmul_rn(thi, INV2PI);
    fi = __fsub_rn(fi, floorf(fi));
    int ii = (int)floorf(__fmul_rn(fi, LUTN_F));
    ii = ii < 0 ? 0 : (ii > 4095 ? 4095 : ii);
    float ci = cosf(__fmul_rn((float)ii, ANG_STEP));

    int base = (b * SS + s) * D2;

    __nv_bfloat16 h, l;
    h = __float2bfloat16_rn(cr); l = __float2bfloat16_rn(cr - __bfloat162float(h));
    g_Qh[base + d] = h; g_Ql[base + d] = l;
    h = __float2bfloat16_rn(ci); l = __float2bfloat16_rn(ci - __bfloat162float(h));
    g_Qh[base + d + DD] = h; g_Ql[base + d + DD] = l;
    h = __float2bfloat16_rn(xr); l = __float2bfloat16_rn(xr - __bfloat162float(h));
    g_Kh[base + d] = h; g_Kl[base + d] = l;
    h = __float2bfloat16_rn(xi); l = __float2bfloat16_rn(xi - __bfloat162float(h));
    g_Kh[base + d + DD] = h; g_Kl[base + d + DD] = l;
}

// ============ Kernel 2: causal flash attention (mma.sync bf16 split, split-KV x2,
//              cp.async 3-slot K ring) ============
__global__ __launch_bounds__(256, 1) void attn_mma() {
    extern __shared__ char sm[];
    const uint32_t su = smem_u32(sm);
    const uint32_t sQh_u = su + OFF_QH, sQl_u = su + OFF_QL;

    const int tid  = threadIdx.x;
    const int wid  = tid >> 5;
    const int lane = tid & 31;
    const int lr = lane & 7, q4 = lane >> 3;
    const int g  = lane >> 2, t = lane & 3;

    const int bid = blockIdx.x;
    const int m   = 63 - (bid >> 2);      // longest tiles first
    const int b   = (bid >> 1) & 1;
    const int sid = bid & 1;
    const int q0  = m << 7;
    const int j0  = sid * (m + 1);
    const int j1  = j0 + (m + 1);

    const char* Qhg = (const char*)(g_Qh + b * (SS * D2) + q0 * D2);
    const char* Qlg = (const char*)(g_Ql + b * (SS * D2) + q0 * D2);
    const char* Khg = (const char*)(g_Kh + b * (SS * D2));
    const char* Klg = (const char*)(g_Kl + b * (SS * D2));

    // ---- load Q tiles (128 rows x 256B), swizzled ----
    for (int e = tid; e < 2048; e += 256) {
        int r = e >> 4, u = e & 15;
        int so = r * 256 + ((u ^ (r & 7)) << 4);
        int go = r * 256 + u * 16;
        *(uint4*)(sm + OFF_QH + so) = *(const uint4*)(Qhg + go);
        *(uint4*)(sm + OFF_QL + so) = *(const uint4*)(Qlg + go);
    }

    // ---- prologue: prefetch first two K tiles into ring slots 0,1 ----
    issue_ktile(Khg, Klg, su + OFFK(0), j0 << 6, tid);
    asm volatile("cp.async.commit_group;" ::: "memory");
    if (j0 + 1 < j1) {
        issue_ktile(Khg, Klg, su + OFFK(1), (j0 + 1) << 6, tid);
        asm volatile("cp.async.commit_group;" ::: "memory");
    }

    // A-frag (Q) lane addressing
    const int rowA = wid * 16 + lr + 8 * (q4 & 1);
    const int swA = rowA & 7;
    const int unitAx = q4 >> 1;
    const uint32_t aRow = (uint32_t)rowA * 256u;
    // B-frag (K rows as n) lane addressing
    const int rowBo = lr + 8 * (q4 >> 1);
    const int unitBx = q4 & 1;
    // V-frag (trans) lane addressing
    const int rowVo = lr + 8 * (q4 & 1);
    const int unitVx = q4 >> 1;

    float o[16][4];
    #pragma unroll
    for (int i = 0; i < 16; i++)
        #pragma unroll
        for (int c = 0; c < 4; c++) o[i][c] = 0.f;
    float l0 = 0.f, l1 = 0.f;

    const float SC = 0.0883883476483184405501f;  // 1/sqrt(128)
    const int row0 = q0 + wid * 16 + g;

    for (int j = j0; j < j1; ++j) {
        const int idx  = j - j0;
        const int slot = idx % 3;
        const uint32_t kb  = su + (uint32_t)OFFK(slot);       // KH base
        const uint32_t kbl = kb + 16384u;                     // KL base

        // wait for tile j (allow tile j+1 still in flight), then block-sync
        if (j + 1 < j1) asm volatile("cp.async.wait_group 1;" ::: "memory");
        else            asm volatile("cp.async.wait_group 0;" ::: "memory");
        __syncthreads();

        const int k0 = j << 6;

        // ---- QK: S[16x64] = Qh.Kh + Qh.Kl + Ql.Kh ----
        float s[8][4];
        #pragma unroll
        for (int i = 0; i < 8; i++)
            #pragma unroll
            for (int c = 0; c < 4; c++) s[i][c] = 0.f;

        #pragma unroll
        for (int kbk = 0; kbk < 8; kbk++) {
            uint32_t aH[4], aL[4];
            uint32_t ao = aRow + (uint32_t)(((2 * kbk + unitAx) ^ swA) << 4);
            ldsm4(aH, sQh_u + ao);
            ldsm4(aL, sQl_u + ao);
            #pragma unroll
            for (int nb2 = 0; nb2 < 4; nb2++) {
                int rB = nb2 * 16 + rowBo;
                uint32_t bo = (uint32_t)(rB * 256 + (((2 * kbk + unitBx) ^ (rB & 7)) << 4));
                uint32_t bH[4], bL[4];
                ldsm4(bH, kb + bo);
                ldsm4(bL, kbl + bo);
                mma16816(s[2 * nb2],     aH, &bH[0]);
                mma16816(s[2 * nb2],     aH, &bL[0]);
                mma16816(s[2 * nb2],     aL, &bH[0]);
                mma16816(s[2 * nb2 + 1], aH, &bH[2]);
                mma16816(s[2 * nb2 + 1], aH, &bL[2]);
                mma16816(s[2 * nb2 + 1], aL, &bH[2]);
            }
        }

        // ---- epilogue: mask + exp + build P frags in registers ----
        uint32_t ph0[8], ph1[8], pl0[8], pl1[8];
        const bool full = (k0 + 63 <= q0 + wid * 16);
        #pragma unroll
        for (int nb = 0; nb < 8; nb++) {
            float e0, e1, e2, e3;
            if (full) {
                e0 = __expf(s[nb][0] * SC);
                e1 = __expf(s[nb][1] * SC);
                e2 = __expf(s[nb][2] * SC);
                e3 = __expf(s[nb][3] * SC);
            } else {
                int col = k0 + nb * 8 + 2 * t;
                e0 = (col     <= row0    ) ? __expf(s[nb][0] * SC) : 0.f;
                e1 = (col + 1 <= row0    ) ? __expf(s[nb][1] * SC) : 0.f;
                e2 = (col     <= row0 + 8) ? __expf(s[nb][2] * SC) : 0.f;
                e3 = (col + 1 <= row0 + 8) ? __expf(s[nb][3] * SC) : 0.f;
            }
            l0 += e0 + e1;
            l1 += e2 + e3;
            split2(e0, e1, ph0[nb], pl0[nb]);
            split2(e2, e3, ph1[nb], pl1[nb]);
        }

        // ---- PV: O[16x128] += Ph.Vh + Ph.Vl + Pl.Vh  (V = K tile, trans frags) ----
        #pragma unroll
        for (int kbk = 0; kbk < 4; kbk++) {
            uint32_t aPh[4] = { ph0[2 * kbk], ph1[2 * kbk], ph0[2 * kbk + 1], ph1[2 * kbk + 1] };
            uint32_t aPl[4] = { pl0[2 * kbk], pl1[2 * kbk], pl0[2 * kbk + 1], pl1[2 * kbk + 1] };
            #pragma unroll
            for (int db2 = 0; db2 < 8; db2++) {
                int rV = kbk * 16 + rowVo;
                uint32_t vo = (uint32_t)(rV * 256 + (((2 * db2 + unitVx) ^ (rV & 7)) << 4));
                uint32_t bH[4], bL[4];
                ldsm4t(bH, kb + vo);
                ldsm4t(bL, kbl + vo);
                mma16816(o[2 * db2],     aPh, &bH[0]);
                mma16816(o[2 * db2],     aPh, &bL[0]);
                mma16816(o[2 * db2],     aPl, &bH[0]);
                mma16816(o[2 * db2 + 1], aPh, &bH[2]);
                mma16816(o[2 * db2 + 1], aPh, &bL[2]);
                mma16816(o[2 * db2 + 1], aPl, &bH[2]);
            }
        }

        // ---- prefetch tile j+2 into slot (idx+2)%3 (read last in iter j-1;
        //      all warps passed this iter's top barrier, so it is free) ----
        if (j + 2 < j1) {
            issue_ktile(Khg, Klg, su + (uint32_t)OFFK((idx + 2) % 3), (j + 2) << 6, tid);
            asm volatile("cp.async.commit_group;" ::: "memory");
        }
    }

    // ---- row-sum reduce (across the 4 lanes sharing a row) ----
    l0 += __shfl_xor_sync(0xffffffffu, l0, 1);
    l0 += __shfl_xor_sync(0xffffffffu, l0, 2);
    l1 += __shfl_xor_sync(0xffffffffu, l1, 1);
    l1 += __shfl_xor_sync(0xffffffffu, l1, 2);

    // ---- fold (c and c+64) in registers, write unnormalized folded O + lsums ----
    float* Og = &g_O[sid][b * (SS * DD)];
    #pragma unroll
    for (int dt = 0; dt < 8; dt++) {
        int c = dt * 8 + 2 * t;   // 0..63
        float f0 = o[dt][0] + o[dt + 8][0];
        float f1 = o[dt][1] + o[dt + 8][1];
        float f2 = o[dt][2] + o[dt + 8][2];
        float f3 = o[dt][3] + o[dt + 8][3];
        *(float2*)(Og + row0 * DD + c)       = make_float2(f0, f1);
        *(float2*)(Og + (row0 + 8) * DD + c) = make_float2(f2, f3);
    }
    if (t == 0) {
        g_Ls[sid][b * SS + row0]     = l0;
        g_Ls[sid][b * SS + row0 + 8] = l1;
    }
}

// ------ Kernel 3: combine splits + chunked EMA (windowed, batch-prefetched) ------
__global__ __launch_bounds__(64, 1) void ema_chunk_kernel(
        const float* __restrict__ alpha_p, float* __restrict__ out) {
    const int d     = threadIdx.x;              // 0..63
    const int b     = blockIdx.x >> 6;
    const int chunk = blockIdx.x & 63;

    const float alpha = alpha_p[0];
    const float a  = 1.0f / (1.0f + expf(-alpha));
    const float na = 1.0f - a;

    // adaptive lookback: (1-a)^lb <= 2^-40, rounded to 8, clamped
    float dl = -log2f(na);
    int lb = (int)ceilf(40.0f / fmaxf(dl, 1e-6f));
    lb = (lb + 7) & ~7;
    lb = lb < 8 ? 8 : (lb > 2048 ? 2048 : lb);

    const int t0     = chunk * EMA_CHUNK;
    int tstart       = t0 - lb;
    if (tstart < 0) tstart = 0;
    const int tend   = t0 + EMA_CHUNK;

    const float* __restrict__ O0 = &g_O[0][b * (SS * DD)];
    const float* __restrict__ O1 = &g_O[1][b * (SS * DD)];
    const float* __restrict__ L0 = &g_Ls[0][b * SS];
    const float* __restrict__ L1 = &g_Ls[1][b * SS];
    float* __restrict__ Ob = out + b * (SS * DD);

    float e = 0.f;
    for (int t = tstart; t < tend; t += 8) {
        float z[8];
        #pragma unroll
        for (int i = 0; i < 8; i++) {
            const int tt = t + i;
            float num = O0[tt * DD + d] + O1[tt * DD + d];
            z[i] = num / (L0[tt] + L1[tt]);
        }
        #pragma unroll
        for (int i = 0; i < 8; i++) {
            e = a * z[i] + na * e;
            if (t + i >= t0) Ob[(t + i) * DD + d] = e;
        }
    }
}

// -------------------- launch --------------------
extern "C" void kernel_launch(void* const* d_in, const int* in_sizes, int n_in,
                              void* d_out, int out_size) {
    const float* sr    = (const float*)d_in[0];
    const float* si    = (const float*)d_in[1];
    const float* pos   = (const float*)d_in[2];
    const float* w_q   = (const float*)d_in[3];
    const float* b_q   = (const float*)d_in[4];
    const float* alpha = (const float*)d_in[5];
    float* out = (float*)d_out;

    (void)in_sizes; (void)n_in; (void)out_size;

    cudaFuncSetAttribute(attn_mma,
                         cudaFuncAttributeMaxDynamicSharedMemorySize, SM_BYTES);

    const int nprep = BB * SS * DD;
    prep_kernel<<<(nprep + 255) / 256, 256>>>(sr, si, pos, w_q, b_q);
    attn_mma<<<256, 256, SM_BYTES>>>();
    ema_chunk_kernel<<<BB * EMA_NCHUNK, 64>>>(alpha, out);
}